// round 16
// baseline (speedup 1.0000x reference)
#include <cuda_runtime.h>

// MSFNO1d: B=32, L=4096, H=64, NL=4, modes {512,1024,2048}
#define BB 32
#define HH 64
#define LL 4096
#define NF 2048

typedef unsigned long long ull;

// ---- scratch (SoA planes for spectral data) ----
__device__ float  g_v[BB*HH*LL];
__device__ float  g_s[BB*HH*LL];
__device__ float  g_Xr[HH*BB*NF];         // Re rfft(v)  [i][b][f]
__device__ float  g_Xi[HH*BB*NF];         // Im
__device__ float  g_Yr[HH*BB*NF];         // Re mixed    [o][b][f]
__device__ float  g_Yi[HH*BB*NF];         // Im
__device__ float2 g_twF[2048];            // e^{-2pi i k/2048}
__device__ float2 g_tw4096[2048];         // e^{-2pi i k/4096}

// ---- helpers ----
__device__ __forceinline__ ull pack2(float lo, float hi){
    ull r; asm("mov.b64 %0,{%1,%2};" : "=l"(r) : "f"(lo), "f"(hi)); return r;
}
__device__ __forceinline__ float2 unpack2(ull v){
    float2 r; asm("mov.b64 {%0,%1},%2;" : "=f"(r.x), "=f"(r.y) : "l"(v)); return r;
}
__device__ __forceinline__ void fma2(ull &acc, ull a, ull b){
    asm("fma.rn.f32x2 %0,%1,%2,%0;" : "+l"(acc) : "l"(a), "l"(b));
}
__device__ __forceinline__ float2 cadd(float2 a, float2 b){
    ull ua, ub, ur;
    asm("mov.b64 %0,{%1,%2};" : "=l"(ua) : "f"(a.x), "f"(a.y));
    asm("mov.b64 %0,{%1,%2};" : "=l"(ub) : "f"(b.x), "f"(b.y));
    asm("add.rn.f32x2 %0,%1,%2;" : "=l"(ur) : "l"(ua), "l"(ub));
    return unpack2(ur);
}
__device__ __forceinline__ float2 csub(float2 a, float2 b){
    const ull NEG1 = 0xBF800000BF800000ULL;
    ull ua, ub, ur;
    asm("mov.b64 %0,{%1,%2};" : "=l"(ua) : "f"(a.x), "f"(a.y));
    asm("mov.b64 %0,{%1,%2};" : "=l"(ub) : "f"(b.x), "f"(b.y));
    asm("fma.rn.f32x2 %0,%1,%2,%3;" : "=l"(ur) : "l"(ub), "l"(NEG1), "l"(ua));
    return unpack2(ur);
}
__device__ __forceinline__ float2 cmul(float2 a, float2 b){
    return make_float2(a.x*b.x - a.y*b.y, a.x*b.y + a.y*b.x);
}
__device__ __forceinline__ float tanh_fast(float x){
    float y; asm("tanh.approx.f32 %0,%1;" : "=f"(y) : "f"(x)); return y;
}
__device__ __forceinline__ float gelu_tanh(float x){
    float x3 = x*x*x;
    return 0.5f*x*(1.0f + tanh_fast(0.7978845608028654f*(x + 0.044715f*x3)));
}
__device__ __forceinline__ void cpasync16(unsigned dst, const void* src){
    asm volatile("cp.async.cg.shared.global [%0], [%1], 16;" :: "r"(dst), "l"(src));
}
#define CP_COMMIT() asm volatile("cp.async.commit_group;")

// ---- twiddle init ----
__global__ void init_tw_kernel(){
    int k = blockIdx.x*256 + threadIdx.x;
    if (k < 2048){
        double s, c; sincospi(-2.0*(double)k/2048.0, &s, &c);
        g_twF[k] = make_float2((float)c, (float)s);
        double s2, c2; sincospi(-2.0*(double)k/4096.0, &s2, &c2);
        g_tw4096[k] = make_float2((float)c2, (float)s2);
    }
}

// ---- encoder ----
__global__ void encoder_kernel(const float* __restrict__ u, const float* __restrict__ x,
                               const float* __restrict__ ew, const float* __restrict__ eb){
    int b = blockIdx.y;
    int t = blockIdx.x*256 + threadIdx.x;
    float xv = x[(size_t)b*LL + t];
    float u0 = u[((size_t)b*3 + 0)*LL + t];
    float u1 = u[((size_t)b*3 + 1)*LL + t];
    float u2 = u[((size_t)b*3 + 2)*LL + t];
    #pragma unroll 4
    for (int h = 0; h < HH; h++){
        float r = eb[h] + ew[h*4+0]*xv + ew[h*4+1]*u0 + ew[h*4+2]*u1 + ew[h*4+3]*u2;
        g_v[((size_t)b*HH + h)*LL + t] = r;
    }
}

// ===================== Stockham radix-8 FFT, float2 smem (N=2048, 256 thr) ==============
template<int MODE> __device__ __forceinline__ int swz(int a){
    if (MODE==1) return a ^ ((a>>4) & 7);
    if (MODE==2) return a ^ (((a>>6) & 1) << 3);
    return a;
}

__device__ __forceinline__ void radix8(const float2* x, float2* c){
    const float r = 0.70710678118654752f;
    float2 y0 = cadd(x[0],x[4]), y4 = csub(x[0],x[4]);
    float2 y1 = cadd(x[1],x[5]), t5 = csub(x[1],x[5]);
    float2 y2 = cadd(x[2],x[6]), t6 = csub(x[2],x[6]);
    float2 y3 = cadd(x[3],x[7]), t7 = csub(x[3],x[7]);
    float2 y5 = make_float2(r*(t5.x+t5.y), r*(t5.y-t5.x));
    float2 y6 = make_float2(t6.y, -t6.x);
    float2 y7 = make_float2(r*(t7.y-t7.x), -r*(t7.x+t7.y));
    float2 z0 = cadd(y0,y2), z2 = csub(y0,y2);
    float2 z1 = cadd(y1,y3), t3 = csub(y1,y3);
    float2 z3 = make_float2(t3.y, -t3.x);
    float2 z4 = cadd(y4,y6), z6 = csub(y4,y6);
    float2 z5 = cadd(y5,y7), u7 = csub(y5,y7);
    float2 z7 = make_float2(u7.y, -u7.x);
    c[0] = cadd(z0,z1); c[4] = csub(z0,z1);
    c[2] = cadd(z2,z3); c[6] = csub(z2,z3);
    c[1] = cadd(z4,z5); c[5] = csub(z4,z5);
    c[3] = cadd(z6,z7); c[7] = csub(z6,z7);
}

__device__ __forceinline__ void twchain(float2* c, float2 w1){
    float2 w2 = cmul(w1, w1);
    float2 w3 = cmul(w2, w1);
    float2 w4 = cmul(w2, w2);
    float2 w5 = cmul(w2, w3);
    float2 w6 = cmul(w3, w3);
    float2 w7 = cmul(w3, w4);
    c[1] = cmul(c[1], w1);
    c[2] = cmul(c[2], w2);
    c[3] = cmul(c[3], w3);
    c[4] = cmul(c[4], w4);
    c[5] = cmul(c[5], w5);
    c[6] = cmul(c[6], w6);
    c[7] = cmul(c[7], w7);
}

template<int LOGS, int TSTR, int SWIN, int SWOUT>
__device__ __forceinline__ void stage8s(const float2* Si, float2* So, int tid){
    int q = tid & ((1<<LOGS)-1);
    int p = tid >> LOGS;
    int base = q + (p << LOGS);
    float2 a[8], c[8];
    #pragma unroll
    for (int j = 0; j < 8; j++) a[j] = Si[swz<SWIN>(base + 256*j)];
    radix8(a, c);
    twchain(c, g_twF[p*TSTR]);
    #pragma unroll
    for (int k = 0; k < 8; k++) So[swz<SWOUT>(q + ((8*p + k) << LOGS))] = c[k];
}

__device__ __forceinline__ void stage8g(const float2* __restrict__ src,
                                        float2* So, int tid){
    float2 a[8], c[8];
    #pragma unroll
    for (int j = 0; j < 8; j++) a[j] = src[tid + 256*j];
    radix8(a, c);
    twchain(c, g_twF[tid]);
    #pragma unroll
    for (int k = 0; k < 8; k++) So[swz<1>(8*tid + k)] = c[k];
}

__device__ __forceinline__ void stage4s(const float2* Si, float2* So, int tid){
    #pragma unroll
    for (int h = 0; h < 2; h++){
        int q = tid + 256*h;
        float2 x0 = Si[q], x1 = Si[q+512], x2 = Si[q+1024], x3 = Si[q+1536];
        float2 y0 = cadd(x0,x2), y2 = csub(x0,x2);
        float2 y1 = cadd(x1,x3), t3 = csub(x1,x3);
        float2 y3 = make_float2(t3.y, -t3.x);
        So[q]      = cadd(y0,y1);
        So[q+512]  = cadd(y2,y3);
        So[q+1024] = csub(y0,y1);
        So[q+1536] = csub(y2,y3);
    }
}

// ---- forward rfft ----
__global__ __launch_bounds__(256, 4) void fft_fwd_kernel(){
    __shared__ float2 SA[2048], SB[2048];
    int b = blockIdx.x, ch = blockIdx.y;
    int tid = threadIdx.x;
    const float2* src = (const float2*)(g_v + ((size_t)b*HH + ch)*LL);
    stage8g(src, SA, tid);
    __syncthreads();
    stage8s<3,8,1,2>(SA, SB, tid);
    __syncthreads();
    stage8s<6,64,2,0>(SB, SA, tid);
    __syncthreads();
    stage4s(SA, SB, tid);
    __syncthreads();
    float* dR = g_Xr + ((size_t)ch*BB + b)*NF;
    float* dI = g_Xi + ((size_t)ch*BB + b)*NF;
    #pragma unroll
    for (int r = 0; r < 8; r++){
        int k = tid + 256*r;
        float2 Zk = SB[k];
        float2 Zn = SB[(2048 - k) & 2047];
        float2 Fe = make_float2(0.5f*(Zk.x + Zn.x),  0.5f*(Zk.y - Zn.y));
        float2 Fo = make_float2(0.5f*(Zk.y + Zn.y), -0.5f*(Zk.x - Zn.x));
        float2 t  = cmul(g_tw4096[k], Fo);
        dR[k] = Fe.x + t.x;
        dI[k] = Fe.y + t.y;
    }
}

// ---- inverse rfft + bias -> g_s ----
__global__ __launch_bounds__(256, 4) void fft_inv_kernel(const float* __restrict__ sb0,
                                                         const float* __restrict__ sb1,
                                                         const float* __restrict__ sb2, int l){
    __shared__ float2 SA[2048], SB[2048];
    int b = blockIdx.x, o = blockIdx.y;
    int tid = threadIdx.x;
    const float* sR = g_Yr + ((size_t)o*BB + b)*NF;
    const float* sI = g_Yi + ((size_t)o*BB + b)*NF;
    #pragma unroll
    for (int r = 0; r < 8; r++){
        int k = tid + 256*r;
        float2 Xk = make_float2(sR[k], sI[k]);
        float2 Xn;
        if (k == 0){ Xk.y = 0.0f; Xn = make_float2(0.0f, 0.0f); }
        else        { Xn = make_float2(sR[2048 - k], sI[2048 - k]); }
        float2 Fe = make_float2(0.5f*(Xk.x + Xn.x), 0.5f*(Xk.y - Xn.y));
        float2 D  = make_float2(0.5f*(Xk.x - Xn.x), 0.5f*(Xk.y + Xn.y));
        float2 w  = g_tw4096[k];
        float2 Fo = make_float2(D.x*w.x + D.y*w.y, D.y*w.x - D.x*w.y);
        SA[k] = make_float2(Fe.x - Fo.y, -(Fe.y + Fo.x));
    }
    __syncthreads();
    stage8s<0,1,0,1>(SA, SB, tid);
    __syncthreads();
    stage8s<3,8,1,2>(SB, SA, tid);
    __syncthreads();
    stage8s<6,64,2,0>(SA, SB, tid);
    __syncthreads();
    stage4s(SB, SA, tid);
    __syncthreads();
    float bias = sb0[l*HH + o] + sb1[l*HH + o] + sb2[l*HH + o];
    float2* dst = (float2*)(g_s + ((size_t)b*HH + o)*LL);
    const float sc = 1.0f/2048.0f;
    #pragma unroll
    for (int r = 0; r < 8; r++){
        int n = tid + 256*r;
        float2 R = SA[n];
        dst[n] = make_float2(R.x*sc + bias, -R.y*sc + bias);
    }
}

// ===================== spectral mixing (R15, unchanged) ==============
__global__ __launch_bounds__(256, 2) void spec_gemm_kernel(const float* __restrict__ w0,
                                                           const float* __restrict__ w1,
                                                           const float* __restrict__ w2, int l){
    extern __shared__ float sm[];
    float*  XsR = sm;
    float*  XsI = sm + 4096;
    float2* W2s = (float2*)(sm + 8192);
    float2* W1s = (float2*)(sm + 12288);
    float2* W0s = (float2*)(sm + 16384);
    float*  WsR = sm + 20480;
    float*  WsI = sm + 21504;
    unsigned sb = (unsigned)__cvta_generic_to_shared(sm);

    int bh = blockIdx.x * 16;
    int o0 = blockIdx.y * 8;
    int f0 = blockIdx.z * 64;
    int tid  = threadIdx.x;
    int lane = tid & 31;
    int g    = tid >> 5;
    int b0   = (g & 3) * 4;
    int oo   = (g >> 2) * 4;
    bool p1 = (f0 < 1024), p0 = (f0 < 512);
    const float2* W2p = (const float2*)w2 + (size_t)l*HH*HH*2048;
    const float2* W1p = (const float2*)w1 + (size_t)l*HH*HH*1024;
    const float2* W0p = (const float2*)w0 + (size_t)l*HH*HH*512;

    ull accR[4][4], accI[4][4];
    #pragma unroll
    for (int bi = 0; bi < 4; bi++)
        #pragma unroll
        for (int oi = 0; oi < 4; oi++){ accR[bi][oi] = 0ull; accI[bi][oi] = 0ull; }

    #define STAGE(c, bufs) do{                                                          \
        int i0s = (c)*2;                                                                \
        _Pragma("unroll")                                                               \
        for (int r = 0; r < 2; r++){                                                    \
            int idx = tid + 256*r;                                                      \
            int ii = idx >> 8, bbq = (idx >> 4) & 15, fq = (idx & 15) * 4;              \
            size_t xofs = ((size_t)(i0s+ii)*BB + bh + bbq)*NF + f0 + fq;                \
            unsigned xslot = ((((bufs)*2 + ii)*16 + bbq)*64 + fq)*4u;                   \
            cpasync16(sb + xslot,          g_Xr + xofs);                                \
            cpasync16(sb + 16384u + xslot, g_Xi + xofs);                                \
            int wii = idx >> 8, wo = (idx >> 5) & 7, wq = (idx & 31) * 2;               \
            size_t wb = ((size_t)(i0s+wii)*HH + o0 + wo);                               \
            unsigned wslot = ((((bufs)*2 + wii)*8 + wo)*64 + wq)*8u;                    \
            cpasync16(sb + 32768u + wslot, W2p + wb*2048 + f0 + wq);                    \
            if (p1) cpasync16(sb + 49152u + wslot, W1p + wb*1024 + f0 + wq);            \
            if (p0) cpasync16(sb + 65536u + wslot, W0p + wb*512  + f0 + wq);            \
        }                                                                               \
    } while(0)

    STAGE(0, 0);
    CP_COMMIT();

    for (int c = 0; c < 32; c++){
        int buf = c & 1;
        __syncthreads();
        if (c < 31){
            STAGE(c+1, buf^1);
            CP_COMMIT();
            asm volatile("cp.async.wait_group 1;");
        } else {
            asm volatile("cp.async.wait_group 0;");
        }
        __syncthreads();
        #pragma unroll
        for (int r = 0; r < 4; r++){
            int idx = tid + 256*r;
            int ii = idx >> 9, o = (idx >> 6) & 7, fi = idx & 63;
            int ws = ((buf*2 + ii)*8 + o)*64 + fi;
            float2 wv = W2s[ws];
            if (p1) wv = cadd(wv, W1s[ws]);
            if (p0) wv = cadd(wv, W0s[ws]);
            WsR[(ii*8 + o)*64 + fi] = wv.x;
            WsI[(ii*8 + o)*64 + fi] = wv.y;
        }
        __syncthreads();
        #pragma unroll
        for (int ii = 0; ii < 2; ii++){
            ull wr[4], wi[4];
            #pragma unroll
            for (int oi = 0; oi < 4; oi++){
                wr[oi] = *(const ull*)&WsR[((ii*8) + oo + oi)*64 + 2*lane];
                wi[oi] = *(const ull*)&WsI[((ii*8) + oo + oi)*64 + 2*lane];
            }
            #pragma unroll
            for (int bi = 0; bi < 4; bi++){
                int xs = ((buf*2 + ii)*16 + b0 + bi)*64 + 2*lane;
                ull xr  = *(const ull*)&XsR[xs];
                ull xi  = *(const ull*)&XsI[xs];
                ull xin = xi ^ 0x8000000080000000ULL;
                #pragma unroll
                for (int oi = 0; oi < 4; oi++){
                    fma2(accR[bi][oi], xr,  wr[oi]);
                    fma2(accR[bi][oi], xin, wi[oi]);
                    fma2(accI[bi][oi], xr,  wi[oi]);
                    fma2(accI[bi][oi], xi,  wr[oi]);
                }
            }
        }
    }
    #undef STAGE

    #pragma unroll
    for (int bi = 0; bi < 4; bi++)
        #pragma unroll
        for (int oi = 0; oi < 4; oi++){
            size_t ofs = ((size_t)(o0 + oo + oi)*BB + bh + b0 + bi)*NF + f0 + 2*lane;
            *(ull*)&g_Yr[ofs] = accR[bi][oi];
            *(ull*)&g_Yi[ofs] = accI[bi][oi];
        }
}

// ===================== pointwise v2: warp-uniform W broadcast ==========================
// v += conv2(gelu(conv1(s))). Block: 256 thr, t-tile 128. Warp g owns 8 output channels
// (o = g*8 + oi) -> W loads are warp-uniform LDS.128 (smem broadcast, ~0 crossbar).
// W staged transposed AND pre-duplicated as (w,w) ull pairs: no pack in hot loop.
// dyn smem: ss[64][128] floats @0 (32KB) | Wtp ull[64][66] @8192 floats (33KB) = 65KB.
__global__ __launch_bounds__(256, 3) void pointwise_kernel(const float* __restrict__ w1,
                                                           const float* __restrict__ b1,
                                                           const float* __restrict__ w2,
                                                           const float* __restrict__ b2, int l){
    extern __shared__ float pws[];
    float* ss  = pws;                 // [64][128]
    ull*   Wtp = (ull*)(pws + 8192);  // [64][66] (row stride 66 -> 528B, 16B aligned)
    int b  = blockIdx.y;
    int t0 = blockIdx.x * 128;
    int tid = threadIdx.x;
    int ts  = tid & 31;
    int og  = tid >> 5;               // warp id = o-group

    // stage s tile (float4) + W1 transposed/duplicated
    #pragma unroll
    for (int r = 0; r < 8; r++){
        int idx = tid + 256*r;                    // over 2048 float4
        int i = idx >> 5, c4 = idx & 31;
        *(float4*)&ss[i*128 + c4*4] =
            *(const float4*)&g_s[((size_t)b*HH + i)*LL + t0 + c4*4];
    }
    #pragma unroll
    for (int r = 0; r < 16; r++){
        int idx = tid + 256*r;                    // idx = o*64 + i
        float w = w1[(size_t)l*4096 + idx];
        Wtp[(idx & 63)*66 + (idx >> 6)] = pack2(w, w);
    }
    __syncthreads();

    ull acc[8][2];
    #pragma unroll
    for (int oi = 0; oi < 8; oi++){
        float bv = b1[l*HH + og*8 + oi];
        acc[oi][0] = pack2(bv, bv);
        acc[oi][1] = acc[oi][0];
    }
    for (int i = 0; i < 64; i++){
        const ull* wrow = &Wtp[i*66 + og*8];      // warp-uniform
        ull w8[8];
        *(float4*)&w8[0] = *(const float4*)&wrow[0];
        *(float4*)&w8[2] = *(const float4*)&wrow[2];
        *(float4*)&w8[4] = *(const float4*)&wrow[4];
        *(float4*)&w8[6] = *(const float4*)&wrow[6];
        ull sv0 = *(const ull*)&ss[i*128 + 2*ts];
        ull sv1 = *(const ull*)&ss[i*128 + 2*ts + 64];
        #pragma unroll
        for (int oi = 0; oi < 8; oi++){
            fma2(acc[oi][0], w8[oi], sv0);
            fma2(acc[oi][1], w8[oi], sv1);
        }
    }
    __syncthreads();   // done reading ss & Wtp
    // gelu -> ss (rows become hidden channels), stage W2
    #pragma unroll
    for (int oi = 0; oi < 8; oi++){
        int o = og*8 + oi;
        #pragma unroll
        for (int j = 0; j < 2; j++){
            float2 a = unpack2(acc[oi][j]);
            *(float2*)&ss[o*128 + 2*ts + 64*j] = make_float2(gelu_tanh(a.x), gelu_tanh(a.y));
        }
    }
    #pragma unroll
    for (int r = 0; r < 16; r++){
        int idx = tid + 256*r;
        float w = w2[(size_t)l*4096 + idx];
        Wtp[(idx & 63)*66 + (idx >> 6)] = pack2(w, w);
    }
    __syncthreads();

    ull acc2[8][2];
    #pragma unroll
    for (int ci = 0; ci < 8; ci++){
        float bv = b2[l*HH + og*8 + ci];
        acc2[ci][0] = pack2(bv, bv);
        acc2[ci][1] = acc2[ci][0];
    }
    for (int h = 0; h < 64; h++){
        const ull* wrow = &Wtp[h*66 + og*8];
        ull w8[8];
        *(float4*)&w8[0] = *(const float4*)&wrow[0];
        *(float4*)&w8[2] = *(const float4*)&wrow[2];
        *(float4*)&w8[4] = *(const float4*)&wrow[4];
        *(float4*)&w8[6] = *(const float4*)&wrow[6];
        ull hv0 = *(const ull*)&ss[h*128 + 2*ts];
        ull hv1 = *(const ull*)&ss[h*128 + 2*ts + 64];
        #pragma unroll
        for (int ci = 0; ci < 8; ci++){
            fma2(acc2[ci][0], w8[ci], hv0);
            fma2(acc2[ci][1], w8[ci], hv1);
        }
    }
    #pragma unroll
    for (int ci = 0; ci < 8; ci++){
        int c = og*8 + ci;
        #pragma unroll
        for (int j = 0; j < 2; j++){
            float2 a = unpack2(acc2[ci][j]);
            float2* vp = (float2*)&g_v[((size_t)b*HH + c)*LL + t0 + 2*ts + 64*j];
            float2 vv = *vp;
            vv.x += a.x; vv.y += a.y;
            *vp = vv;
        }
    }
}

// ---- decoder ----
__global__ void decoder_kernel(const float* __restrict__ dw, const float* __restrict__ db,
                               float* __restrict__ out){
    int b = blockIdx.y;
    int t = blockIdx.x*256 + threadIdx.x;
    float acc = db[0];
    #pragma unroll 8
    for (int h = 0; h < HH; h++)
        acc += dw[h] * g_v[((size_t)b*HH + h)*LL + t];
    out[(size_t)b*LL + t] = acc;
}

extern "C" void kernel_launch(void* const* d_in, const int* in_sizes, int n_in,
                              void* d_out, int out_size){
    const float* u     = (const float*)d_in[0];
    const float* x     = (const float*)d_in[1];
    const float* enc_w = (const float*)d_in[2];
    const float* enc_b = (const float*)d_in[3];
    const float* dec_w = (const float*)d_in[4];
    const float* dec_b = (const float*)d_in[5];
    const float* c1w   = (const float*)d_in[6];
    const float* c1b   = (const float*)d_in[7];
    const float* c2w   = (const float*)d_in[8];
    const float* c2b   = (const float*)d_in[9];
    const float* sw0   = (const float*)d_in[10];
    const float* sb0   = (const float*)d_in[11];
    const float* sw1   = (const float*)d_in[12];
    const float* sb1   = (const float*)d_in[13];
    const float* sw2   = (const float*)d_in[14];
    const float* sb2   = (const float*)d_in[15];
    float* out = (float*)d_out;

    const int SMEM_SPEC = 22528 * 4;              // 88KB
    const int SMEM_PW   = 8192*4 + 64*66*8;       // 32KB + 33KB = 66560B
    cudaFuncSetAttribute(spec_gemm_kernel,
                         cudaFuncAttributeMaxDynamicSharedMemorySize, SMEM_SPEC);
    cudaFuncSetAttribute(pointwise_kernel,
                         cudaFuncAttributeMaxDynamicSharedMemorySize, SMEM_PW);

    init_tw_kernel<<<8, 256>>>();
    encoder_kernel<<<dim3(LL/256, BB), 256>>>(u, x, enc_w, enc_b);
    for (int l = 0; l < 4; l++){
        fft_fwd_kernel<<<dim3(BB, HH), 256>>>();
        spec_gemm_kernel<<<dim3(2, HH/8, NF/64), 256, SMEM_SPEC>>>(sw0, sw1, sw2, l);
        fft_inv_kernel<<<dim3(BB, HH), 256>>>(sb0, sb1, sb2, l);
        pointwise_kernel<<<dim3(LL/128, BB), 256, SMEM_PW>>>(c1w, c1b, c2w, c2b, l);
    }
    decoder_kernel<<<dim3(LL/256, BB), 256>>>(dec_w, dec_b, out);
}

// round 17
// speedup vs baseline: 1.0723x; 1.0723x over previous
#include <cuda_runtime.h>

// MSFNO1d: B=32, L=4096, H=64, NL=4, modes {512,1024,2048}
#define BB 32
#define HH 64
#define LL 4096
#define NF 2048

typedef unsigned long long ull;

// ---- scratch (SoA planes for spectral data) ----
__device__ float  g_v[BB*HH*LL];
__device__ float  g_s[BB*HH*LL];
__device__ float  g_Xr[HH*BB*NF];         // Re rfft(v)  [i][b][f]
__device__ float  g_Xi[HH*BB*NF];         // Im
__device__ float  g_Yr[HH*BB*NF];         // Re mixed    [o][b][f]
__device__ float  g_Yi[HH*BB*NF];         // Im
__device__ __align__(16) float2 g_twF[2048];     // e^{-2pi i k/2048}
__device__ __align__(16) float2 g_tw4096[2048];  // e^{-2pi i k/4096}

// ---- helpers ----
__device__ __forceinline__ ull pack2(float lo, float hi){
    ull r; asm("mov.b64 %0,{%1,%2};" : "=l"(r) : "f"(lo), "f"(hi)); return r;
}
__device__ __forceinline__ float2 unpack2(ull v){
    float2 r; asm("mov.b64 {%0,%1},%2;" : "=f"(r.x), "=f"(r.y) : "l"(v)); return r;
}
__device__ __forceinline__ void fma2(ull &acc, ull a, ull b){
    asm("fma.rn.f32x2 %0,%1,%2,%0;" : "+l"(acc) : "l"(a), "l"(b));
}
__device__ __forceinline__ float2 cadd(float2 a, float2 b){
    ull ua, ub, ur;
    asm("mov.b64 %0,{%1,%2};" : "=l"(ua) : "f"(a.x), "f"(a.y));
    asm("mov.b64 %0,{%1,%2};" : "=l"(ub) : "f"(b.x), "f"(b.y));
    asm("add.rn.f32x2 %0,%1,%2;" : "=l"(ur) : "l"(ua), "l"(ub));
    return unpack2(ur);
}
__device__ __forceinline__ float2 csub(float2 a, float2 b){
    const ull NEG1 = 0xBF800000BF800000ULL;
    ull ua, ub, ur;
    asm("mov.b64 %0,{%1,%2};" : "=l"(ua) : "f"(a.x), "f"(a.y));
    asm("mov.b64 %0,{%1,%2};" : "=l"(ub) : "f"(b.x), "f"(b.y));
    asm("fma.rn.f32x2 %0,%1,%2,%3;" : "=l"(ur) : "l"(ub), "l"(NEG1), "l"(ua));
    return unpack2(ur);
}
__device__ __forceinline__ float2 cmul(float2 a, float2 b){
    return make_float2(a.x*b.x - a.y*b.y, a.x*b.y + a.y*b.x);
}
__device__ __forceinline__ float tanh_fast(float x){
    float y; asm("tanh.approx.f32 %0,%1;" : "=f"(y) : "f"(x)); return y;
}
__device__ __forceinline__ float gelu_tanh(float x){
    float x3 = x*x*x;
    return 0.5f*x*(1.0f + tanh_fast(0.7978845608028654f*(x + 0.044715f*x3)));
}
__device__ __forceinline__ void cpasync16(unsigned dst, const void* src){
    asm volatile("cp.async.cg.shared.global [%0], [%1], 16;" :: "r"(dst), "l"(src));
}
#define CP_COMMIT() asm volatile("cp.async.commit_group;")

// ---- twiddle init ----
__global__ void init_tw_kernel(){
    int k = blockIdx.x*256 + threadIdx.x;
    if (k < 2048){
        double s, c; sincospi(-2.0*(double)k/2048.0, &s, &c);
        g_twF[k] = make_float2((float)c, (float)s);
        double s2, c2; sincospi(-2.0*(double)k/4096.0, &s2, &c2);
        g_tw4096[k] = make_float2((float)c2, (float)s2);
    }
}

// ---- encoder ----
__global__ void encoder_kernel(const float* __restrict__ u, const float* __restrict__ x,
                               const float* __restrict__ ew, const float* __restrict__ eb){
    int b = blockIdx.y;
    int t = blockIdx.x*256 + threadIdx.x;
    float xv = x[(size_t)b*LL + t];
    float u0 = u[((size_t)b*3 + 0)*LL + t];
    float u1 = u[((size_t)b*3 + 1)*LL + t];
    float u2 = u[((size_t)b*3 + 2)*LL + t];
    #pragma unroll 4
    for (int h = 0; h < HH; h++){
        float r = eb[h] + ew[h*4+0]*xv + ew[h*4+1]*u0 + ew[h*4+2]*u1 + ew[h*4+3]*u2;
        g_v[((size_t)b*HH + h)*LL + t] = r;
    }
}

// ===================== Stockham radix-8 FFT, float2 smem (N=2048, 256 thr) ==============
template<int MODE> __device__ __forceinline__ int swz(int a){
    if (MODE==1) return a ^ ((a>>4) & 7);
    if (MODE==2) return a ^ (((a>>6) & 1) << 3);
    return a;
}

__device__ __forceinline__ void radix8(const float2* x, float2* c){
    const float r = 0.70710678118654752f;
    float2 y0 = cadd(x[0],x[4]), y4 = csub(x[0],x[4]);
    float2 y1 = cadd(x[1],x[5]), t5 = csub(x[1],x[5]);
    float2 y2 = cadd(x[2],x[6]), t6 = csub(x[2],x[6]);
    float2 y3 = cadd(x[3],x[7]), t7 = csub(x[3],x[7]);
    float2 y5 = make_float2(r*(t5.x+t5.y), r*(t5.y-t5.x));
    float2 y6 = make_float2(t6.y, -t6.x);
    float2 y7 = make_float2(r*(t7.y-t7.x), -r*(t7.x+t7.y));
    float2 z0 = cadd(y0,y2), z2 = csub(y0,y2);
    float2 z1 = cadd(y1,y3), t3 = csub(y1,y3);
    float2 z3 = make_float2(t3.y, -t3.x);
    float2 z4 = cadd(y4,y6), z6 = csub(y4,y6);
    float2 z5 = cadd(y5,y7), u7 = csub(y5,y7);
    float2 z7 = make_float2(u7.y, -u7.x);
    c[0] = cadd(z0,z1); c[4] = csub(z0,z1);
    c[2] = cadd(z2,z3); c[6] = csub(z2,z3);
    c[1] = cadd(z4,z5); c[5] = csub(z4,z5);
    c[3] = cadd(z6,z7); c[7] = csub(z6,z7);
}

__device__ __forceinline__ void twchain(float2* c, float2 w1){
    float2 w2 = cmul(w1, w1);
    float2 w3 = cmul(w2, w1);
    float2 w4 = cmul(w2, w2);
    float2 w5 = cmul(w2, w3);
    float2 w6 = cmul(w3, w3);
    float2 w7 = cmul(w3, w4);
    c[1] = cmul(c[1], w1);
    c[2] = cmul(c[2], w2);
    c[3] = cmul(c[3], w3);
    c[4] = cmul(c[4], w4);
    c[5] = cmul(c[5], w5);
    c[6] = cmul(c[6], w6);
    c[7] = cmul(c[7], w7);
}

template<int LOGS, int TSTR, int SWIN, int SWOUT>
__device__ __forceinline__ void stage8s(const float2* Si, float2* So, int tid){
    int q = tid & ((1<<LOGS)-1);
    int p = tid >> LOGS;
    int base = q + (p << LOGS);
    float2 a[8], c[8];
    #pragma unroll
    for (int j = 0; j < 8; j++) a[j] = Si[swz<SWIN>(base + 256*j)];
    radix8(a, c);
    twchain(c, g_twF[p*TSTR]);
    #pragma unroll
    for (int k = 0; k < 8; k++) So[swz<SWOUT>(q + ((8*p + k) << LOGS))] = c[k];
}

__device__ __forceinline__ void stage8g(const float2* __restrict__ src,
                                        float2* So, int tid){
    float2 a[8], c[8];
    #pragma unroll
    for (int j = 0; j < 8; j++) a[j] = src[tid + 256*j];
    radix8(a, c);
    twchain(c, g_twF[tid]);
    #pragma unroll
    for (int k = 0; k < 8; k++) So[swz<1>(8*tid + k)] = c[k];
}

__device__ __forceinline__ void stage4s(const float2* Si, float2* So, int tid){
    #pragma unroll
    for (int h = 0; h < 2; h++){
        int q = tid + 256*h;
        float2 x0 = Si[q], x1 = Si[q+512], x2 = Si[q+1024], x3 = Si[q+1536];
        float2 y0 = cadd(x0,x2), y2 = csub(x0,x2);
        float2 y1 = cadd(x1,x3), t3 = csub(x1,x3);
        float2 y3 = make_float2(t3.y, -t3.x);
        So[q]      = cadd(y0,y1);
        So[q+512]  = cadd(y2,y3);
        So[q+1024] = csub(y0,y1);
        So[q+1536] = csub(y2,y3);
    }
}

// ---- forward rfft: v row (4096 real) -> SoA planes; vectorized pair epilogue ----
__global__ __launch_bounds__(256, 4) void fft_fwd_kernel(){
    __shared__ __align__(16) float2 SA[2048];
    __shared__ __align__(16) float2 SB[2048];
    int b = blockIdx.x, ch = blockIdx.y;
    int tid = threadIdx.x;
    const float2* src = (const float2*)(g_v + ((size_t)b*HH + ch)*LL);
    stage8g(src, SA, tid);
    __syncthreads();
    stage8s<3,8,1,2>(SA, SB, tid);
    __syncthreads();
    stage8s<6,64,2,0>(SB, SA, tid);
    __syncthreads();
    stage4s(SA, SB, tid);
    __syncthreads();
    float* dR = g_Xr + ((size_t)ch*BB + b)*NF;
    float* dI = g_Xi + ((size_t)ch*BB + b)*NF;
    const float4* SB4 = (const float4*)SB;
    const float4* TW4 = (const float4*)g_tw4096;
    #pragma unroll
    for (int r = 0; r < 4; r++){
        int m = tid + 256*r;                      // freq pair (2m, 2m+1)
        float4 zp  = SB4[m];
        float2 Zn0 = SB[(2048 - 2*m) & 2047];
        float2 Zn1 = SB[2047 - 2*m];
        float4 tw  = TW4[m];
        float2 Fe0 = make_float2(0.5f*(zp.x + Zn0.x),  0.5f*(zp.y - Zn0.y));
        float2 Fo0 = make_float2(0.5f*(zp.y + Zn0.y), -0.5f*(zp.x - Zn0.x));
        float2 t0v = cmul(make_float2(tw.x, tw.y), Fo0);
        float2 Fe1 = make_float2(0.5f*(zp.z + Zn1.x),  0.5f*(zp.w - Zn1.y));
        float2 Fo1 = make_float2(0.5f*(zp.w + Zn1.y), -0.5f*(zp.z - Zn1.x));
        float2 t1v = cmul(make_float2(tw.z, tw.w), Fo1);
        *(float2*)&dR[2*m] = make_float2(Fe0.x + t0v.x, Fe1.x + t1v.x);
        *(float2*)&dI[2*m] = make_float2(Fe0.y + t0v.y, Fe1.y + t1v.y);
    }
}

// ---- inverse rfft + bias -> g_s; vectorized pair prologue/epilogue ----
__global__ __launch_bounds__(256, 4) void fft_inv_kernel(const float* __restrict__ sb0,
                                                         const float* __restrict__ sb1,
                                                         const float* __restrict__ sb2, int l){
    __shared__ __align__(16) float2 SA[2048];
    __shared__ __align__(16) float2 SB[2048];
    int b = blockIdx.x, o = blockIdx.y;
    int tid = threadIdx.x;
    const float* sR = g_Yr + ((size_t)o*BB + b)*NF;
    const float* sI = g_Yi + ((size_t)o*BB + b)*NF;
    const float2* sR2 = (const float2*)sR;
    const float2* sI2 = (const float2*)sI;
    const float4* TW4 = (const float4*)g_tw4096;
    float4* SA4 = (float4*)SA;
    #pragma unroll
    for (int r = 0; r < 4; r++){
        int m = tid + 256*r;                      // freq pair (2m, 2m+1)
        float2 xr = sR2[m];
        float2 xi = sI2[m];
        float Xk0i = xi.x, Xn0r, Xn0i;
        if (m == 0){ Xk0i = 0.0f; Xn0r = 0.0f; Xn0i = 0.0f; }
        else       { Xn0r = sR[2048 - 2*m]; Xn0i = sI[2048 - 2*m]; }
        float Xn1r = sR[2047 - 2*m], Xn1i = sI[2047 - 2*m];
        float4 tw = TW4[m];
        float2 Fe0 = make_float2(0.5f*(xr.x + Xn0r), 0.5f*(Xk0i - Xn0i));
        float2 D0  = make_float2(0.5f*(xr.x - Xn0r), 0.5f*(Xk0i + Xn0i));
        float2 Fo0 = make_float2(D0.x*tw.x + D0.y*tw.y, D0.y*tw.x - D0.x*tw.y);
        float2 Fe1 = make_float2(0.5f*(xr.y + Xn1r), 0.5f*(xi.y - Xn1i));
        float2 D1  = make_float2(0.5f*(xr.y - Xn1r), 0.5f*(xi.y + Xn1i));
        float2 Fo1 = make_float2(D1.x*tw.z + D1.y*tw.w, D1.y*tw.z - D1.x*tw.w);
        SA4[m] = make_float4(Fe0.x - Fo0.y, -(Fe0.y + Fo0.x),
                             Fe1.x - Fo1.y, -(Fe1.y + Fo1.x));
    }
    __syncthreads();
    stage8s<0,1,0,1>(SA, SB, tid);
    __syncthreads();
    stage8s<3,8,1,2>(SB, SA, tid);
    __syncthreads();
    stage8s<6,64,2,0>(SA, SB, tid);
    __syncthreads();
    stage4s(SB, SA, tid);
    __syncthreads();
    float bias = sb0[l*HH + o] + sb1[l*HH + o] + sb2[l*HH + o];
    float4* dst4 = (float4*)(g_s + ((size_t)b*HH + o)*LL);
    const float4* SA4c = (const float4*)SA;
    const float sc = 1.0f/2048.0f;
    #pragma unroll
    for (int r = 0; r < 4; r++){
        int m = tid + 256*r;
        float4 Rq = SA4c[m];
        dst4[m] = make_float4(Rq.x*sc + bias, -Rq.y*sc + bias,
                              Rq.z*sc + bias, -Rq.w*sc + bias);
    }
}

// ===================== spectral mixing (R15, unchanged) ==============
__global__ __launch_bounds__(256, 2) void spec_gemm_kernel(const float* __restrict__ w0,
                                                           const float* __restrict__ w1,
                                                           const float* __restrict__ w2, int l){
    extern __shared__ float sm[];
    float*  XsR = sm;
    float*  XsI = sm + 4096;
    float2* W2s = (float2*)(sm + 8192);
    float2* W1s = (float2*)(sm + 12288);
    float2* W0s = (float2*)(sm + 16384);
    float*  WsR = sm + 20480;
    float*  WsI = sm + 21504;
    unsigned sb = (unsigned)__cvta_generic_to_shared(sm);

    int bh = blockIdx.x * 16;
    int o0 = blockIdx.y * 8;
    int f0 = blockIdx.z * 64;
    int tid  = threadIdx.x;
    int lane = tid & 31;
    int g    = tid >> 5;
    int b0   = (g & 3) * 4;
    int oo   = (g >> 2) * 4;
    bool p1 = (f0 < 1024), p0 = (f0 < 512);
    const float2* W2p = (const float2*)w2 + (size_t)l*HH*HH*2048;
    const float2* W1p = (const float2*)w1 + (size_t)l*HH*HH*1024;
    const float2* W0p = (const float2*)w0 + (size_t)l*HH*HH*512;

    ull accR[4][4], accI[4][4];
    #pragma unroll
    for (int bi = 0; bi < 4; bi++)
        #pragma unroll
        for (int oi = 0; oi < 4; oi++){ accR[bi][oi] = 0ull; accI[bi][oi] = 0ull; }

    #define STAGE(c, bufs) do{                                                          \
        int i0s = (c)*2;                                                                \
        _Pragma("unroll")                                                               \
        for (int r = 0; r < 2; r++){                                                    \
            int idx = tid + 256*r;                                                      \
            int ii = idx >> 8, bbq = (idx >> 4) & 15, fq = (idx & 15) * 4;              \
            size_t xofs = ((size_t)(i0s+ii)*BB + bh + bbq)*NF + f0 + fq;                \
            unsigned xslot = ((((bufs)*2 + ii)*16 + bbq)*64 + fq)*4u;                   \
            cpasync16(sb + xslot,          g_Xr + xofs);                                \
            cpasync16(sb + 16384u + xslot, g_Xi + xofs);                                \
            int wii = idx >> 8, wo = (idx >> 5) & 7, wq = (idx & 31) * 2;               \
            size_t wb = ((size_t)(i0s+wii)*HH + o0 + wo);                               \
            unsigned wslot = ((((bufs)*2 + wii)*8 + wo)*64 + wq)*8u;                    \
            cpasync16(sb + 32768u + wslot, W2p + wb*2048 + f0 + wq);                    \
            if (p1) cpasync16(sb + 49152u + wslot, W1p + wb*1024 + f0 + wq);            \
            if (p0) cpasync16(sb + 65536u + wslot, W0p + wb*512  + f0 + wq);            \
        }                                                                               \
    } while(0)

    STAGE(0, 0);
    CP_COMMIT();

    for (int c = 0; c < 32; c++){
        int buf = c & 1;
        __syncthreads();
        if (c < 31){
            STAGE(c+1, buf^1);
            CP_COMMIT();
            asm volatile("cp.async.wait_group 1;");
        } else {
            asm volatile("cp.async.wait_group 0;");
        }
        __syncthreads();
        #pragma unroll
        for (int r = 0; r < 4; r++){
            int idx = tid + 256*r;
            int ii = idx >> 9, o = (idx >> 6) & 7, fi = idx & 63;
            int ws = ((buf*2 + ii)*8 + o)*64 + fi;
            float2 wv = W2s[ws];
            if (p1) wv = cadd(wv, W1s[ws]);
            if (p0) wv = cadd(wv, W0s[ws]);
            WsR[(ii*8 + o)*64 + fi] = wv.x;
            WsI[(ii*8 + o)*64 + fi] = wv.y;
        }
        __syncthreads();
        #pragma unroll
        for (int ii = 0; ii < 2; ii++){
            ull wr[4], wi[4];
            #pragma unroll
            for (int oi = 0; oi < 4; oi++){
                wr[oi] = *(const ull*)&WsR[((ii*8) + oo + oi)*64 + 2*lane];
                wi[oi] = *(const ull*)&WsI[((ii*8) + oo + oi)*64 + 2*lane];
            }
            #pragma unroll
            for (int bi = 0; bi < 4; bi++){
                int xs = ((buf*2 + ii)*16 + b0 + bi)*64 + 2*lane;
                ull xr  = *(const ull*)&XsR[xs];
                ull xi  = *(const ull*)&XsI[xs];
                ull xin = xi ^ 0x8000000080000000ULL;
                #pragma unroll
                for (int oi = 0; oi < 4; oi++){
                    fma2(accR[bi][oi], xr,  wr[oi]);
                    fma2(accR[bi][oi], xin, wi[oi]);
                    fma2(accI[bi][oi], xr,  wi[oi]);
                    fma2(accI[bi][oi], xi,  wr[oi]);
                }
            }
        }
    }
    #undef STAGE

    #pragma unroll
    for (int bi = 0; bi < 4; bi++)
        #pragma unroll
        for (int oi = 0; oi < 4; oi++){
            size_t ofs = ((size_t)(o0 + oo + oi)*BB + bh + b0 + bi)*NF + f0 + 2*lane;
            *(ull*)&g_Yr[ofs] = accR[bi][oi];
            *(ull*)&g_Yi[ofs] = accI[bi][oi];
        }
}

// ---- pointwise (R15 exact): v += conv2(gelu(conv1(s))); register-tiled 4o x 8t ----
__global__ __launch_bounds__(256) void pointwise_kernel(const float* __restrict__ w1,
                                                        const float* __restrict__ b1,
                                                        const float* __restrict__ w2,
                                                        const float* __restrict__ b2, int l){
    int b  = blockIdx.y;
    int t0 = blockIdx.x * 128;
    __shared__ float ss[64][128];
    __shared__ float Wb[64][64];
    int tid = threadIdx.x;
    int ts  = tid & 15;
    int og  = tid >> 4;

    #pragma unroll
    for (int r = 0; r < 16; r++){
        int idx = tid + 256*r;
        int i = idx >> 6, c2 = idx & 63;
        *(float2*)&ss[i][c2*2] = *(const float2*)&g_s[((size_t)b*HH + i)*LL + t0 + c2*2];
    }
    #pragma unroll
    for (int r = 0; r < 16; r++){
        int idx = tid + 256*r;
        Wb[idx >> 6][idx & 63] = w1[(size_t)l*4096 + idx];
    }
    __syncthreads();

    ull acc[4][4];
    #pragma unroll
    for (int oi = 0; oi < 4; oi++){
        float bv = b1[l*HH + og*4 + oi];
        #pragma unroll
        for (int j = 0; j < 4; j++) acc[oi][j] = pack2(bv, bv);
    }
    for (int i = 0; i < 64; i++){
        ull sv[4];
        #pragma unroll
        for (int j = 0; j < 4; j++) sv[j] = *(const ull*)&ss[i][2*ts + 32*j];
        #pragma unroll
        for (int oi = 0; oi < 4; oi++){
            float w = Wb[og*4 + oi][i];
            ull wp = pack2(w, w);
            #pragma unroll
            for (int j = 0; j < 4; j++) fma2(acc[oi][j], wp, sv[j]);
        }
    }
    __syncthreads();
    #pragma unroll
    for (int oi = 0; oi < 4; oi++)
        #pragma unroll
        for (int j = 0; j < 4; j++){
            float2 a = unpack2(acc[oi][j]);
            ss[og*4 + oi][2*ts + 32*j]     = gelu_tanh(a.x);
            ss[og*4 + oi][2*ts + 32*j + 1] = gelu_tanh(a.y);
        }
    #pragma unroll
    for (int r = 0; r < 16; r++){
        int idx = tid + 256*r;
        Wb[idx >> 6][idx & 63] = w2[(size_t)l*4096 + idx];
    }
    __syncthreads();

    ull acc2[4][4];
    #pragma unroll
    for (int ci = 0; ci < 4; ci++){
        float bv = b2[l*HH + og*4 + ci];
        #pragma unroll
        for (int j = 0; j < 4; j++) acc2[ci][j] = pack2(bv, bv);
    }
    for (int o = 0; o < 64; o++){
        ull hv[4];
        #pragma unroll
        for (int j = 0; j < 4; j++) hv[j] = *(const ull*)&ss[o][2*ts + 32*j];
        #pragma unroll
        for (int ci = 0; ci < 4; ci++){
            float w = Wb[og*4 + ci][o];
            ull wp = pack2(w, w);
            #pragma unroll
            for (int j = 0; j < 4; j++) fma2(acc2[ci][j], wp, hv[j]);
        }
    }
    #pragma unroll
    for (int ci = 0; ci < 4; ci++){
        int c = og*4 + ci;
        #pragma unroll
        for (int j = 0; j < 4; j++){
            float2 a = unpack2(acc2[ci][j]);
            float2* vp = (float2*)(g_v + ((size_t)b*HH + c)*LL + t0 + 2*ts + 32*j);
            float2 vv = *vp;
            vv.x += a.x; vv.y += a.y;
            *vp = vv;
        }
    }
}

// ---- decoder ----
__global__ void decoder_kernel(const float* __restrict__ dw, const float* __restrict__ db,
                               float* __restrict__ out){
    int b = blockIdx.y;
    int t = blockIdx.x*256 + threadIdx.x;
    float acc = db[0];
    #pragma unroll 8
    for (int h = 0; h < HH; h++)
        acc += dw[h] * g_v[((size_t)b*HH + h)*LL + t];
    out[(size_t)b*LL + t] = acc;
}

extern "C" void kernel_launch(void* const* d_in, const int* in_sizes, int n_in,
                              void* d_out, int out_size){
    const float* u     = (const float*)d_in[0];
    const float* x     = (const float*)d_in[1];
    const float* enc_w = (const float*)d_in[2];
    const float* enc_b = (const float*)d_in[3];
    const float* dec_w = (const float*)d_in[4];
    const float* dec_b = (const float*)d_in[5];
    const float* c1w   = (const float*)d_in[6];
    const float* c1b   = (const float*)d_in[7];
    const float* c2w   = (const float*)d_in[8];
    const float* c2b   = (const float*)d_in[9];
    const float* sw0   = (const float*)d_in[10];
    const float* sb0   = (const float*)d_in[11];
    const float* sw1   = (const float*)d_in[12];
    const float* sb1   = (const float*)d_in[13];
    const float* sw2   = (const float*)d_in[14];
    const float* sb2   = (const float*)d_in[15];
    float* out = (float*)d_out;

    const int SMEM_SPEC = 22528 * 4;   // 88KB dynamic
    cudaFuncSetAttribute(spec_gemm_kernel,
                         cudaFuncAttributeMaxDynamicSharedMemorySize, SMEM_SPEC);

    init_tw_kernel<<<8, 256>>>();
    encoder_kernel<<<dim3(LL/256, BB), 256>>>(u, x, enc_w, enc_b);
    for (int l = 0; l < 4; l++){
        fft_fwd_kernel<<<dim3(BB, HH), 256>>>();
        spec_gemm_kernel<<<dim3(2, HH/8, NF/64), 256, SMEM_SPEC>>>(sw0, sw1, sw2, l);
        fft_inv_kernel<<<dim3(BB, HH), 256>>>(sb0, sb1, sb2, l);
        pointwise_kernel<<<dim3(LL/128, BB), 256>>>(c1w, c1b, c2w, c2b, l);
    }
    decoder_kernel<<<dim3(LL/256, BB), 256>>>(dec_w, dec_b, out);
}